// round 8
// baseline (speedup 1.0000x reference)
#include <cuda_runtime.h>
#include <cuda_bf16.h>
#include <cstdint>

// ---------------- problem constants ----------------
#define NROI   256
#define CCH    1024
#define FH     100
#define FW     50
#define HWPIX  (FH*FW)            // 5000
#define POOLN  7
#define KDIM   (CCH*POOLN*POOLN)  // 50176
#define NHID   1024
#define NCLS   21

// ---------------- GEMM config ----------------
#define SPLITS 28
#define KC     (KDIM/SPLITS)      // 1792
#define KB     16                 // fp32 K elements per stage (one k16 mma step)
#define NSTG   (KC/KB)            // 112
#define BM     128
#define BN     128
#define NTH    512
// bf16 elems per smem row: 16 data + 8 pad = 48 BYTES -> every ldmatrix row
// address is 16B-aligned; rows hit distinct 16B segments mod 128B (proven R6).
#define LDS_ROW 24

// ---------------- scratch (allocation-free rule: __device__ globals) ----------------
__device__ float g_fmT[HWPIX*CCH];                    // ~20.5 MB
__device__ float g_P[(size_t)NROI*KDIM];              // ~51.4 MB
__device__ float g_part[(size_t)SPLITS*NROI*NHID];    // ~29.4 MB
__device__ float g_r[NROI*NHID];                      // 1 MB

// ---------------- helpers ----------------
__device__ __forceinline__ uint32_t smem_u32(const void* p) {
    uint32_t a;
    asm("{ .reg .u64 t; cvta.to.shared.u64 t, %1; cvt.u32.u64 %0, t; }" : "=r"(a) : "l"(p));
    return a;
}

__device__ __forceinline__ void ldsm4(uint32_t* r, uint32_t addr) {
    asm volatile("ldmatrix.sync.aligned.m8n8.x4.shared.b16 {%0,%1,%2,%3}, [%4];"
        : "=r"(r[0]), "=r"(r[1]), "=r"(r[2]), "=r"(r[3]) : "r"(addr));
}

__device__ __forceinline__ void hmma(float* c, const uint32_t* a, const uint32_t* b) {
    asm volatile("mma.sync.aligned.m16n8k16.row.col.f32.bf16.bf16.f32 "
        "{%0,%1,%2,%3}, {%4,%5,%6,%7}, {%8,%9}, {%0,%1,%2,%3};"
        : "+f"(c[0]), "+f"(c[1]), "+f"(c[2]), "+f"(c[3])
        : "r"(a[0]), "r"(a[1]), "r"(a[2]), "r"(a[3]), "r"(b[0]), "r"(b[1]));
}

// fp32 -> (bf16 hi by truncation [exact], bf16 lo rn) for 4 elems; 8B store per plane
__device__ __forceinline__ void cvt_store(float4 v, uint8_t* hi_p, uint8_t* lo_p, uint32_t off) {
    uint32_t u0 = __float_as_uint(v.x), u1 = __float_as_uint(v.y);
    uint32_t u2 = __float_as_uint(v.z), u3 = __float_as_uint(v.w);
    uint32_t h01, h23;
    asm("prmt.b32 %0, %1, %2, 0x7632;" : "=r"(h01) : "r"(u0), "r"(u1));
    asm("prmt.b32 %0, %1, %2, 0x7632;" : "=r"(h23) : "r"(u2), "r"(u3));
    float l0 = v.x - __uint_as_float(u0 & 0xffff0000u);
    float l1 = v.y - __uint_as_float(u1 & 0xffff0000u);
    float l2 = v.z - __uint_as_float(u2 & 0xffff0000u);
    float l3 = v.w - __uint_as_float(u3 & 0xffff0000u);
    uint32_t q01, q23;
    asm("cvt.rn.satfinite.bf16x2.f32 %0, %1, %2;" : "=r"(q01) : "f"(l1), "f"(l0));
    asm("cvt.rn.satfinite.bf16x2.f32 %0, %1, %2;" : "=r"(q23) : "f"(l3), "f"(l2));
    *(uint2*)(hi_p + off) = make_uint2(h01, h23);
    *(uint2*)(lo_p + off) = make_uint2(q01, q23);
}

// ---------------- kernel 0: no-op probe (shifts ncu capture slot onto gemm) ----------------
__global__ void probe_kernel() {}

// ---------------- kernel 1: transpose [C,H,W] -> [HW, C] ----------------
__global__ void transpose_kernel(const float* __restrict__ fm) {
    __shared__ float tile[32][33];
    int p0 = blockIdx.x * 32, c0 = blockIdx.y * 32;
    int x = threadIdx.x, y0 = threadIdx.y;
#pragma unroll
    for (int r = 0; r < 4; r++) {
        int c = c0 + y0 + r * 8, p = p0 + x;
        tile[y0 + r * 8][x] = (p < HWPIX) ? fm[(size_t)c * HWPIX + p] : 0.f;
    }
    __syncthreads();
#pragma unroll
    for (int r = 0; r < 4; r++) {
        int p = p0 + y0 + r * 8, c = c0 + x;
        if (p < HWPIX) g_fmT[(size_t)p * CCH + c] = tile[x][y0 + r * 8];
    }
}

// ---------------- kernel 2: ROI adaptive max-pool ----------------
__global__ __launch_bounds__(256) void pool_kernel(const int* __restrict__ props) {
    int r = blockIdx.x;
    int c = blockIdx.y * 256 + threadIdx.x;
    int x1 = props[4 * r + 0]; if (x1 < 0) x1 = 0;
    int y1 = props[4 * r + 1]; if (y1 < 0) y1 = 0;
    int x2 = props[4 * r + 2]; if (x2 < 0) x2 = 0;
    int y2 = props[4 * r + 3]; if (y2 < 0) y2 = 0;
    int h0 = x1 >> 4, w0 = y1 >> 4, h1 = x2 >> 4, w1 = y2 >> 4;
    int sh = h1 - h0 + 1, sw = w1 - w0 + 1;
    float* out = g_P + (size_t)r * KDIM + (size_t)c * (POOLN * POOLN);
    const float* __restrict__ fT = g_fmT;
    for (int i = 0; i < POOLN; i++) {
        int hs = h0 + (i * sh) / POOLN;
        int he = h0 + ((i + 1) * sh + POOLN - 1) / POOLN;
        for (int j = 0; j < POOLN; j++) {
            int ws = w0 + (j * sw) / POOLN;
            int we = w0 + ((j + 1) * sw + POOLN - 1) / POOLN;
            float m = -3.402823466e+38f;
            for (int h = hs; h < he; h++) {
                const float* row = fT + ((size_t)(h * FW) + ws) * CCH + c;
                for (int w = ws; w < we; w++) { m = fmaxf(m, *row); row += CCH; }
            }
            out[i * POOLN + j] = m;
        }
    }
}

// ---------------- kernel 3: mma.sync bf16 hi/lo split GEMM ----------------
// 512 threads, BM=128 x BN=128, 16 warps (4/SMSP), warp tile 32x32,
// static 48KB double-buffered smem (R6-proven layout). Split-K 28.
// 3 products per k16: AhiWhi + AhiWlo + AloWhi.
__global__ __launch_bounds__(NTH, 1) void gemm_kernel(const float* __restrict__ Wt) {
    __shared__ __align__(16) __nv_bfloat16 smA[2][2][128 * LDS_ROW];   // 24 KB
    __shared__ __align__(16) __nv_bfloat16 smW[2][2][128 * LDS_ROW];   // 24 KB

    int tid = threadIdx.x, lane = tid & 31, wid = tid >> 5;
    int wm = wid >> 2;            // 0..3 : 32-row slice
    int wn = wid & 3;             // 0..3 : 32-col slice
    int nbase = blockIdx.x * BN;
    int mbase = blockIdx.y * BM;
    int z = blockIdx.z;
    size_t kbase = (size_t)z * KC;

    const float* Ab = g_P + (size_t)mbase * KDIM + kbase;
    const float* Wb = Wt  + (size_t)nbase * KDIM + kbase;

    // loads: 512 threads cover 128 rows x 4 float4 each for A and W
    int r0 = tid >> 2, c4 = tid & 3;
    uint32_t offT = (uint32_t)(r0 * LDS_ROW + c4 * 4) * 2;   // bytes

    float acc[2][4][4] = {};

    // prologue: stage 0 into regs
    float4 la = *(const float4*)(Ab + (size_t)r0 * KDIM + c4 * 4);
    float4 lw = *(const float4*)(Wb + (size_t)r0 * KDIM + c4 * 4);

    // per-warp fragment smem byte offsets (within a plane); all 16B-aligned
    uint32_t aoff = (uint32_t)(((wm * 32 + (lane & 15)) * LDS_ROW + ((lane >> 4) & 1) * 8) * 2);
    uint32_t boff = (uint32_t)(((wn * 32 + (lane & 7) + ((lane >> 4) & 1) * 8) * LDS_ROW
                               + ((lane >> 3) & 1) * 8) * 2);
    const uint32_t step16 = 16 * LDS_ROW * 2;   // 768 B

    for (int t = 0; t < NSTG; t++) {
        int b = t & 1;
        cvt_store(la, (uint8_t*)smA[b][0], (uint8_t*)smA[b][1], offT);
        cvt_store(lw, (uint8_t*)smW[b][0], (uint8_t*)smW[b][1], offT);
        if (t + 1 < NSTG) {
            int kt = (t + 1) * KB;
            la = *(const float4*)(Ab + (size_t)r0 * KDIM + kt + c4 * 4);
            lw = *(const float4*)(Wb + (size_t)r0 * KDIM + kt + c4 * 4);
        }
        __syncthreads();

        uint32_t af[2][2][4];                 // [plane][mi][4]
        ldsm4(af[0][0], smem_u32(smA[b][0]) + aoff);
        ldsm4(af[0][1], smem_u32(smA[b][0]) + aoff + step16);
        ldsm4(af[1][0], smem_u32(smA[b][1]) + aoff);
        ldsm4(af[1][1], smem_u32(smA[b][1]) + aoff + step16);
#pragma unroll
        for (int nf = 0; nf < 2; nf++) {      // each ldsm4 = 2 n8 fragments
            uint32_t bh[4], bl[4];
            ldsm4(bh, smem_u32(smW[b][0]) + boff + nf * step16);
            ldsm4(bl, smem_u32(smW[b][1]) + boff + nf * step16);
#pragma unroll
            for (int mi = 0; mi < 2; mi++) {
                hmma(acc[mi][nf * 2],     af[0][mi], bh);       // hi*hi
                hmma(acc[mi][nf * 2],     af[0][mi], bl);       // hi*lo
                hmma(acc[mi][nf * 2],     af[1][mi], bh);       // lo*hi
                hmma(acc[mi][nf * 2 + 1], af[0][mi], bh + 2);
                hmma(acc[mi][nf * 2 + 1], af[0][mi], bl + 2);
                hmma(acc[mi][nf * 2 + 1], af[1][mi], bh + 2);
            }
        }
    }

    // epilogue: write split-K partials
#pragma unroll
    for (int mi = 0; mi < 2; mi++) {
        int row = mbase + wm * 32 + mi * 16 + (lane >> 2);
#pragma unroll
        for (int ni = 0; ni < 4; ni++) {
            int col = nbase + wn * 32 + ni * 8 + (lane & 3) * 2;
            size_t base = ((size_t)z * NROI + row) * NHID + col;
            *(float2*)(g_part + base)            = make_float2(acc[mi][ni][0], acc[mi][ni][1]);
            *(float2*)(g_part + base + 8 * NHID) = make_float2(acc[mi][ni][2], acc[mi][ni][3]);
        }
    }
}

// ---------------- kernel 4: fixed-order split reduction + bias + relu (float4) ----------------
__global__ __launch_bounds__(256) void reduce_kernel(const float* __restrict__ fc_b) {
    int base = (blockIdx.x * 256 + threadIdx.x) * 4;       // < 256*1024
    int n = base & (NHID - 1);
    float4 s = *(const float4*)(fc_b + n);
#pragma unroll 7
    for (int zz = 0; zz < SPLITS; zz++) {
        float4 v = *(const float4*)(g_part + (size_t)zz * NROI * NHID + base);
        s.x += v.x; s.y += v.y; s.z += v.z; s.w += v.w;
    }
    float4 o = make_float4(fmaxf(s.x, 0.f), fmaxf(s.y, 0.f), fmaxf(s.z, 0.f), fmaxf(s.w, 0.f));
    *(float4*)(g_r + base) = o;
}

// ---------------- kernel 5: cls head, argmax, reg gather ----------------
__global__ __launch_bounds__(128) void head_kernel(
    const float* __restrict__ cls_w, const float* __restrict__ cls_b,
    const float* __restrict__ reg_w, const float* __restrict__ reg_b,
    float* __restrict__ out)
{
    __shared__ float rv[NHID];
    __shared__ float clsv[NCLS];
    __shared__ int bestI;
    int r = blockIdx.x, tid = threadIdx.x;
    const float* rr = g_r + (size_t)r * NHID;
    for (int i = tid * 4; i < NHID; i += 128 * 4)
        *(float4*)&rv[i] = *(const float4*)&rr[i];
    __syncthreads();

    int warp = tid >> 5, lane = tid & 31;
    for (int n = warp; n < NCLS; n += 4) {
        const float* wrow = cls_w + (size_t)n * NHID;
        float s = 0.f;
        for (int k = lane; k < NHID; k += 32) s = fmaf(wrow[k], rv[k], s);
#pragma unroll
        for (int o = 16; o; o >>= 1) s += __shfl_xor_sync(0xffffffffu, s, o);
        if (lane == 0) {
            float v = s + cls_b[n];
            clsv[n] = v;
            out[(size_t)r * NCLS + n] = v;
        }
    }
    __syncthreads();
    if (tid == 0) {
        int b = 0; float bvv = clsv[0];
        for (int n = 1; n < NCLS; n++)
            if (clsv[n] > bvv) { bvv = clsv[n]; b = n; }
        bestI = b;
    }
    __syncthreads();
    {
        int rowi = bestI * 4 + warp;
        const float* wrow = reg_w + (size_t)rowi * NHID;
        float s = 0.f;
        for (int k = lane; k < NHID; k += 32) s = fmaf(wrow[k], rv[k], s);
#pragma unroll
        for (int o = 16; o; o >>= 1) s += __shfl_xor_sync(0xffffffffu, s, o);
        if (lane == 0)
            out[(size_t)NROI * NCLS + (size_t)r * 4 + warp] = s + reg_b[rowi];
    }
}

// ---------------- launch ----------------
extern "C" void kernel_launch(void* const* d_in, const int* in_sizes, int n_in,
                              void* d_out, int out_size) {
    const float* fm    = (const float*)d_in[0];
    const int*   props = (const int*)  d_in[1];
    const float* fc_w  = (const float*)d_in[2];
    const float* fc_b  = (const float*)d_in[3];
    const float* cls_w = (const float*)d_in[4];
    const float* cls_b = (const float*)d_in[5];
    const float* reg_w = (const float*)d_in[6];
    const float* reg_b = (const float*)d_in[7];
    float* out = (float*)d_out;

    probe_kernel<<<1, 32>>>();
    transpose_kernel<<<dim3((HWPIX + 31) / 32, CCH / 32), dim3(32, 8)>>>(fm);
    pool_kernel<<<dim3(NROI, CCH / 256), 256>>>(props);
    gemm_kernel<<<dim3(NHID / BN, NROI / BM, SPLITS), NTH>>>(fc_w);
    reduce_kernel<<<(NROI * NHID) / 1024, 256>>>(fc_b);
    head_kernel<<<NROI, 128>>>(cls_w, cls_b, reg_w, reg_b, out);
}